// round 11
// baseline (speedup 1.0000x reference)
#include <cuda_runtime.h>
#include <cuda_fp16.h>
#include <math.h>
#include <stdint.h>

#define NB 8
#define CC 256
#define HH 8
#define DD 32
#define LL 2048
#define SCALE 0.0625f            // C^-0.5 = 1/16
#define LOG2E 1.44269504089f

// Scratch (__device__ globals; allocation-free rule)
__device__ uint4 g_q_u[NB * CC * LL / 8];   // half [nh][l][32], SCALE*LOG2E folded
__device__ uint4 g_k_u[NB * CC * LL / 8];   // half [nh][l][32]
__device__ uint4 g_v_u[NB * CC * LL / 8];   // half [nh][32][l]
__device__ uint4 g_xt [NB * CC * LL / 8];   // half [n][l][256]  x transposed
__device__ uint4 g_aoh[NB * CC * LL / 8];   // half [n][l][256]  attn out
__device__ uint4 g_wh [4 * CC * CC / 8];    // half [w][o][c]    weights fp16

__device__ __forceinline__ void mma_f16(float c[4], const uint32_t a[4],
                                        uint32_t b0, uint32_t b1) {
    asm volatile(
        "mma.sync.aligned.m16n8k16.row.col.f32.f16.f16.f32 "
        "{%0,%1,%2,%3}, {%4,%5,%6,%7}, {%8,%9}, {%0,%1,%2,%3};"
        : "+f"(c[0]), "+f"(c[1]), "+f"(c[2]), "+f"(c[3])
        : "r"(a[0]), "r"(a[1]), "r"(a[2]), "r"(a[3]), "r"(b0), "r"(b1));
}

__device__ __forceinline__ uint32_t packh2(float a, float b) {
    __half2 h = __floats2half2_rn(a, b);
    return *(uint32_t*)&h;
}

__device__ __forceinline__ uint32_t h2ex2(uint32_t x) {
    uint32_t y;
    asm("ex2.approx.f16x2 %0, %1;" : "=r"(y) : "r"(x));
    return y;
}

__device__ __forceinline__ void ldsm_x4(uint32_t& r0, uint32_t& r1,
                                        uint32_t& r2, uint32_t& r3,
                                        uint32_t saddr) {
    asm volatile(
        "ldmatrix.sync.aligned.m8n8.x4.shared.b16 {%0,%1,%2,%3}, [%4];"
        : "=r"(r0), "=r"(r1), "=r"(r2), "=r"(r3) : "r"(saddr));
}

#define CP_ASYNC16(smem_u32, gptr) \
    asm volatile("cp.async.cg.shared.global [%0], [%1], 16;" \
                 :: "r"(smem_u32), "l"(gptr) : "memory")
#define CP_COMMIT()  asm volatile("cp.async.commit_group;" ::: "memory")
#define CP_WAIT0()   asm volatile("cp.async.wait_group 0;" ::: "memory")

// ---------------------------------------------------------------------------
// K0a: weights f32 -> fp16 [w][o][c].  Wq gets SCALE*LOG2E folded.
// ---------------------------------------------------------------------------
__global__ __launch_bounds__(256) void wconv_kernel(
    const float* __restrict__ Wq, const float* __restrict__ Wk,
    const float* __restrict__ Wv, const float* __restrict__ Wo)
{
    const int w = blockIdx.y;
    const float* W = (w == 0) ? Wq : (w == 1) ? Wk : (w == 2) ? Wv : Wo;
    const float s = (w == 0) ? SCALE * LOG2E : 1.0f;
    const int i = (blockIdx.x * 256 + threadIdx.x) * 4;
    const float4 v = *(const float4*)&W[i];
    uint2 h;
    h.x = packh2(v.x * s, v.y * s);
    h.y = packh2(v.z * s, v.w * s);
    *(uint2*)((__half*)g_wh + (size_t)w * CC * CC + i) = h;
}

// ---------------------------------------------------------------------------
// K0b: transpose x [n][c][l] f32 -> xt [n][l][256] fp16
// ---------------------------------------------------------------------------
__global__ __launch_bounds__(256) void transpose_kernel(
    const float* __restrict__ x)
{
    __shared__ float sm[32][33];
    const int l0 = blockIdx.x * 32;
    const int c0 = blockIdx.y * 32;
    const int n  = blockIdx.z;
    const int t  = threadIdx.x;

    const int li = t & 31, ci = t >> 5;
    #pragma unroll
    for (int k = 0; k < 4; k++)
        sm[ci + k * 8][li] = x[((size_t)n * CC + c0 + ci + k * 8) * LL + l0 + li];
    __syncthreads();

    const int l  = t >> 3;
    const int cg = (t & 7) * 4;
    uint2 hi;
    hi.x = packh2(sm[cg + 0][l], sm[cg + 1][l]);
    hi.y = packh2(sm[cg + 2][l], sm[cg + 3][l]);
    *(uint2*)((__half*)g_xt + ((size_t)n * LL + l0 + l) * CC + c0 + cg) = hi;
}

// ---------------------------------------------------------------------------
// 1-pass fp16 GEMM core.  M=128(l) x N=128(o) x K=256, k-chunk 32.
// ---------------------------------------------------------------------------
struct GemmAcc { float c[16][4]; };

__device__ __forceinline__ void gemm_core1(
    const __half* __restrict__ A, const __half* __restrict__ Bsrc,
    __half* Xh, __half* Bh, GemmAcc& R)
{
    const int tid  = threadIdx.x;
    const int warp = tid >> 5;
    const int lane = tid & 31;
    const int gid  = lane >> 2;
    const int tg   = lane & 3;
    const int warp_ml = (warp & 3) * 32;
    const int warp_no = (warp >> 2) * 64;

    const uint32_t* Xh32 = (const uint32_t*)Xh;
    const uint32_t* Bh32 = (const uint32_t*)Bh;

    const int lr = tid >> 1, cp = (tid & 1) * 16;
    uint4 ra0 = *(const uint4*)(A    + (size_t)lr * CC + cp);
    uint4 ra1 = *(const uint4*)(A    + (size_t)lr * CC + cp + 8);
    uint4 rb0 = *(const uint4*)(Bsrc + (size_t)lr * CC + cp);
    uint4 rb1 = *(const uint4*)(Bsrc + (size_t)lr * CC + cp + 8);

    #pragma unroll
    for (int i = 0; i < 16; i++)
        R.c[i][0] = R.c[i][1] = R.c[i][2] = R.c[i][3] = 0.0f;

    for (int kk = 0; kk < CC; kk += 32) {
        if (kk) __syncthreads();
        *(uint4*)&Xh[lr * 40 + cp]     = ra0;
        *(uint4*)&Xh[lr * 40 + cp + 8] = ra1;
        *(uint4*)&Bh[lr * 40 + cp]     = rb0;
        *(uint4*)&Bh[lr * 40 + cp + 8] = rb1;
        __syncthreads();
        if (kk + 32 < CC) {
            ra0 = *(const uint4*)(A    + (size_t)lr * CC + kk + 32 + cp);
            ra1 = *(const uint4*)(A    + (size_t)lr * CC + kk + 32 + cp + 8);
            rb0 = *(const uint4*)(Bsrc + (size_t)lr * CC + kk + 32 + cp);
            rb1 = *(const uint4*)(Bsrc + (size_t)lr * CC + kk + 32 + cp + 8);
        }

        #pragma unroll
        for (int ks = 0; ks < 2; ks++) {
            uint32_t a[2][4];
            #pragma unroll
            for (int mt = 0; mt < 2; mt++) {
                const int r = warp_ml + mt * 16;
                const int b0 = (r + gid) * 20 + ks * 8 + tg;
                const int b8 = (r + gid + 8) * 20 + ks * 8 + tg;
                a[mt][0] = Xh32[b0];     a[mt][1] = Xh32[b8];
                a[mt][2] = Xh32[b0 + 4]; a[mt][3] = Xh32[b8 + 4];
            }
            #pragma unroll
            for (int nt = 0; nt < 8; nt++) {
                const int nb = (warp_no + nt * 8 + gid) * 20 + ks * 8 + tg;
                const uint32_t bb0 = Bh32[nb], bb1 = Bh32[nb + 4];
                #pragma unroll
                for (int mt = 0; mt < 2; mt++)
                    mma_f16(R.c[mt * 8 + nt], a[mt], bb0, bb1);
            }
        }
    }
}

// ---------------------------------------------------------------------------
// K1: qkv projection.  grid (16, 2, 24 = n*3+w), 256 thr.
// ---------------------------------------------------------------------------
__global__ __launch_bounds__(256) void gemm_qkv_tc()
{
    __shared__ __align__(16) __half SM[17408];   // Xh | Bh, reused for O stage
    __half* Xh = SM;
    __half* Bh = SM + 5120;

    const int l0 = blockIdx.x * 128;
    const int ot = blockIdx.y;
    const int z  = blockIdx.z;
    const int n  = z / 3, w = z % 3;

    GemmAcc R;
    gemm_core1((const __half*)g_xt + ((size_t)n * LL + l0) * CC,
               (const __half*)g_wh + ((size_t)w * CC + ot * 128) * CC,
               Xh, Bh, R);

    const int tid  = threadIdx.x;
    const int warp = tid >> 5;
    const int lane = tid & 31;
    const int gid  = lane >> 2;
    const int tg   = lane & 3;
    const int warp_ml = (warp & 3) * 32;
    const int warp_no = (warp >> 2) * 64;

    if (w == 2) {
        __syncthreads();
        #pragma unroll
        for (int mt = 0; mt < 2; mt++)
            #pragma unroll
            for (int nt = 0; nt < 8; nt++) {
                const float* c = R.c[mt * 8 + nt];
                const int ol = warp_no + nt * 8 + 2 * tg;
                const int ll = warp_ml + mt * 16 + gid;
                SM[ol * 136 + ll]           = __float2half_rn(c[0]);
                SM[(ol + 1) * 136 + ll]     = __float2half_rn(c[1]);
                SM[ol * 136 + ll + 8]       = __float2half_rn(c[2]);
                SM[(ol + 1) * 136 + ll + 8] = __float2half_rn(c[3]);
            }
        __syncthreads();
        __half* vd = (__half*)g_v_u + (size_t)n * CC * LL;
        #pragma unroll
        for (int i = 0; i < 8; i++) {
            const int idx = i * 256 + tid;
            const int row = idx >> 4;
            const int col = (idx & 15) * 8;
            uint4 vv = *(uint4*)&SM[row * 136 + col];
            *(uint4*)&vd[(size_t)(ot * 128 + row) * LL + l0 + col] = vv;
        }
    } else {
        __half* qk = (__half*)((w == 0) ? g_q_u : g_k_u);
        #pragma unroll
        for (int mt = 0; mt < 2; mt++)
            #pragma unroll
            for (int nt = 0; nt < 8; nt++) {
                const float* c = R.c[mt * 8 + nt];
                const int o = ot * 128 + warp_no + nt * 8 + 2 * tg;
                const int h = o >> 5, d = o & 31;
                const int l = l0 + warp_ml + mt * 16 + gid;
                const size_t base = (size_t)(n * 8 + h) * LL;
                *(uint32_t*)&qk[(base + l) * 32 + d]     = packh2(c[0], c[1]);
                *(uint32_t*)&qk[(base + l + 8) * 32 + d] = packh2(c[2], c[3]);
            }
    }
}

// ---------------------------------------------------------------------------
// K2: flash attention.  BQ=256 (2 m-tiles/warp: K/V frags reused 2x), BK=128
// per barrier (2 x 64 sub-tiles), double-buffered smem filled by cp.async.cg,
// ldmatrix.x4 fragment loads, interleaved ex2/PV, ones-column row-sum MMA.
// S computed in nt-halves to bound register pressure.  2 CTAs/SM.
// ---------------------------------------------------------------------------
#define KSUB (64 * 72)               // halves per K sub-tile
#define VSUB (32 * 72)               // halves per V sub-tile
#define KSUBB (KSUB * 2)             // bytes
#define VSUBB (VSUB * 2)
#define VBASE (4 * KSUBB)            // V region byte offset
#define ATTN_SMEM_BYTES (4 * KSUBB + 4 * VSUBB)   // 55296 B

__global__ __launch_bounds__(256, 2) void attn_kernel()
{
    extern __shared__ __align__(16) __half sm[];

    const int l0 = blockIdx.x * 256;
    const int nh = blockIdx.y;
    const __half* Qh = (const __half*)g_q_u + (size_t)nh * LL * 32;
    const __half* Kh = (const __half*)g_k_u + (size_t)nh * LL * 32;
    const __half* Vh = (const __half*)g_v_u + (size_t)nh * DD * LL;

    const int tid  = threadIdx.x;
    const int lane = tid & 31;
    const int gid  = lane >> 2;
    const int tg   = lane & 3;
    const int qb   = (tid >> 5) * 32;           // 32 q-rows per warp

    const uint32_t smb   = (uint32_t)__cvta_generic_to_shared(sm);
    const uint32_t ldrow = (lane & 7) * 144 + (lane >> 3) * 16;

    // Staging maps (cp.async, 16B each)
    const int kr   = tid >> 2;            // K row within sub
    const int kc   = tid & 3;             // 16B chunk in row
    const int vd   = tid >> 4;            // V d within 16-row group
    const int vsub = (tid >> 3) & 1;
    const int vci  = tid & 7;
    const uint32_t ksm0 = smb + kr * 144 + kc * 16;
    const uint32_t vsm0 = smb + VBASE + vsub * VSUBB + vd * 144 + vci * 16;

    // Prologue: tile 0 into buffer 0 via cp.async
    #pragma unroll
    for (int i = 0; i < 2; i++) {
        CP_ASYNC16(ksm0 + i * KSUBB, &Kh[(size_t)(i * 64 + kr) * 32 + kc * 8]);
        CP_ASYNC16(vsm0 + i * 16 * 144, &Vh[(size_t)(i * 16 + vd) * LL + (tid & 15) * 8]);
    }
    CP_COMMIT();

    // Q A-frags: 2 m-tiles x 2 k-steps (overlaps with async loads)
    uint32_t aq[2][2][4];
    #pragma unroll
    for (int mt = 0; mt < 2; mt++)
        #pragma unroll
        for (int ks = 0; ks < 2; ks++) {
            const size_t r0 = (size_t)(l0 + qb + mt * 16 + gid) * 32 + ks * 16 + 2 * tg;
            const size_t r8 = r0 + 8 * 32;
            aq[mt][ks][0] = *(const uint32_t*)&Qh[r0];
            aq[mt][ks][1] = *(const uint32_t*)&Qh[r8];
            aq[mt][ks][2] = *(const uint32_t*)&Qh[r0 + 8];
            aq[mt][ks][3] = *(const uint32_t*)&Qh[r8 + 8];
        }

    float o[2][4][4] = {};
    float oS[2][4] = {};
    const uint32_t bones = (gid == 0) ? 0x3C003C00u : 0u;

    CP_WAIT0();
    __syncthreads();

    int p = 0;
    for (int kt = 0; kt < LL; kt += 128, p ^= 1) {
        const bool more = (kt + 128 < LL);
        if (more) {
            const uint32_t kb = ksm0 + (p ^ 1) * 2 * KSUBB;
            const uint32_t vb2 = vsm0 + (p ^ 1) * 2 * VSUBB;
            #pragma unroll
            for (int i = 0; i < 2; i++) {
                CP_ASYNC16(kb + i * KSUBB,
                           &Kh[(size_t)(kt + 128 + i * 64 + kr) * 32 + kc * 8]);
                CP_ASYNC16(vb2 + i * 16 * 144,
                           &Vh[(size_t)(i * 16 + vd) * LL + kt + 128 + (tid & 15) * 8]);
            }
            CP_COMMIT();
        }

        #pragma unroll
        for (int sub = 0; sub < 2; sub++) {
            const uint32_t kA = smb + (p * 2 + sub) * KSUBB + ldrow;
            const uint32_t vA = smb + VBASE + (p * 2 + sub) * VSUBB + ldrow;

            #pragma unroll
            for (int half = 0; half < 2; half++) {
                // S' for nt = 4*half .. 4*half+3, both m-tiles
                float c0[4][4], c1[4][4];
                #pragma unroll
                for (int nt4 = 0; nt4 < 4; nt4++) {
                    uint32_t kb0, kb1, kb2, kb3;
                    ldsm_x4(kb0, kb1, kb2, kb3, kA + (half * 4 + nt4) * 1152);
                    c0[nt4][0] = c0[nt4][1] = c0[nt4][2] = c0[nt4][3] = 0.0f;
                    c1[nt4][0] = c1[nt4][1] = c1[nt4][2] = c1[nt4][3] = 0.0f;
                    mma_f16(c0[nt4], aq[0][0], kb0, kb1);
                    mma_f16(c0[nt4], aq[0][1], kb2, kb3);
                    mma_f16(c1[nt4], aq[1][0], kb0, kb1);
                    mma_f16(c1[nt4], aq[1][1], kb2, kb3);
                }

                // V frags for this half (sp = half), then 2 s-steps
                uint32_t vb[4][4];
                #pragma unroll
                for (int ntv = 0; ntv < 4; ntv++)
                    ldsm_x4(vb[ntv][0], vb[ntv][1], vb[ntv][2], vb[ntv][3],
                            vA + ntv * 1152 + half * 64);

                #pragma unroll
                for (int sh = 0; sh < 2; sh++) {
                    uint32_t pa[4];
                    // m-tile 0
                    pa[0] = h2ex2(packh2(c0[2 * sh][0],     c0[2 * sh][1]));
                    pa[1] = h2ex2(packh2(c0[2 * sh][2],     c0[2 * sh][3]));
                    pa[2] = h2ex2(packh2(c0[2 * sh + 1][0], c0[2 * sh + 1][1]));
                    pa[3] = h2ex2(packh2(c0[2 * sh + 1][2], c0[2 * sh + 1][3]));
                    #pragma unroll
                    for (int ntv = 0; ntv < 4; ntv++)
                        mma_f16(o[0][ntv], pa, vb[ntv][2 * sh], vb[ntv][2 * sh + 1]);
                    mma_f16(oS[0], pa, bones, bones);
                    // m-tile 1
                    pa[0] = h2ex2(packh2(c1[2 * sh][0],     c1[2 * sh][1]));
                    pa[1] = h2ex2(packh2(c1[2 * sh][2],     c1[2 * sh][3]));
                    pa[2] = h2ex2(packh2(c1[2 * sh + 1][0], c1[2 * sh + 1][1]));
                    pa[3] = h2ex2(packh2(c1[2 * sh + 1][2], c1[2 * sh + 1][3]));
                    #pragma unroll
                    for (int ntv = 0; ntv < 4; ntv++)
                        mma_f16(o[1][ntv], pa, vb[ntv][2 * sh], vb[ntv][2 * sh + 1]);
                    mma_f16(oS[1], pa, bones, bones);
                }
            }
        }

        if (more) {
            CP_WAIT0();
            __syncthreads();
        }
    }

    // Epilogue: broadcast row sums from tg==0 lanes, normalize, write fp16
    const int n = nh >> 3, h = nh & 7;
    __half* aoh = (__half*)g_aoh;
    #pragma unroll
    for (int mt = 0; mt < 2; mt++) {
        const float l0v = __shfl_sync(0xffffffffu, oS[mt][0], lane & 28);
        const float l1v = __shfl_sync(0xffffffffu, oS[mt][2], lane & 28);
        const float inv0 = 1.0f / l0v;
        const float inv1 = 1.0f / l1v;
        #pragma unroll
        for (int ntv = 0; ntv < 4; ntv++) {
            const int d = h * 32 + ntv * 8 + 2 * tg;
            const int lr = l0 + qb + mt * 16 + gid;
            const size_t a0 = ((size_t)n * LL + lr) * CC + d;
            const size_t a1 = ((size_t)n * LL + lr + 8) * CC + d;
            *(uint32_t*)&aoh[a0] = packh2(o[mt][ntv][0] * inv0, o[mt][ntv][1] * inv0);
            *(uint32_t*)&aoh[a1] = packh2(o[mt][ntv][2] * inv1, o[mt][ntv][3] * inv1);
        }
    }
}

// ---------------------------------------------------------------------------
// K3: output projection: out = Wo @ ao + bo (f32 out).  grid (16, 2, 8).
// ---------------------------------------------------------------------------
__global__ __launch_bounds__(256) void gemm_proj_tc(
    const float* __restrict__ bo,
    float* __restrict__ out)
{
    __shared__ __align__(16) __half SM[10240];
    __half* Xh = SM;
    __half* Bh = SM + 5120;

    const int l0 = blockIdx.x * 128;
    const int ot = blockIdx.y;
    const int n  = blockIdx.z;

    GemmAcc R;
    gemm_core1((const __half*)g_aoh + ((size_t)n * LL + l0) * CC,
               (const __half*)g_wh + ((size_t)3 * CC + ot * 128) * CC,
               Xh, Bh, R);

    const int tid  = threadIdx.x;
    const int warp = tid >> 5;
    const int lane = tid & 31;
    const int gid  = lane >> 2;
    const int tg   = lane & 3;
    const int warp_ml = (warp & 3) * 32;
    const int warp_no = (warp >> 2) * 64;

    float* base = out + (size_t)n * CC * LL;
    #pragma unroll
    for (int mt = 0; mt < 2; mt++)
        #pragma unroll
        for (int nt = 0; nt < 8; nt++) {
            const float* c = R.c[mt * 8 + nt];
            const int o = ot * 128 + warp_no + nt * 8 + 2 * tg;
            const int l = l0 + warp_ml + mt * 16 + gid;
            const float b0v = bo[o], b1v = bo[o + 1];
            base[(size_t)o * LL + l]           = c[0] + b0v;
            base[(size_t)(o + 1) * LL + l]     = c[1] + b1v;
            base[(size_t)o * LL + l + 8]       = c[2] + b0v;
            base[(size_t)(o + 1) * LL + l + 8] = c[3] + b1v;
        }
}

// ---------------------------------------------------------------------------
extern "C" void kernel_launch(void* const* d_in, const int* in_sizes, int n_in,
                              void* d_out, int out_size)
{
    const float* x  = (const float*)d_in[0];
    const float* Wq = (const float*)d_in[1];
    const float* Wk = (const float*)d_in[2];
    const float* Wv = (const float*)d_in[3];
    const float* Wo = (const float*)d_in[4];
    const float* bo = (const float*)d_in[5];
    float* out = (float*)d_out;

    cudaFuncSetAttribute(attn_kernel,
                         cudaFuncAttributeMaxDynamicSharedMemorySize,
                         ATTN_SMEM_BYTES);

    wconv_kernel<<<dim3(CC * CC / 1024, 4), 256>>>(Wq, Wk, Wv, Wo);
    transpose_kernel<<<dim3(LL / 32, CC / 32, NB), 256>>>(x);
    gemm_qkv_tc<<<dim3(LL / 128, 2, NB * 3), 256>>>();
    attn_kernel<<<dim3(LL / 256, NB * HH), 256, ATTN_SMEM_BYTES>>>();
    gemm_proj_tc<<<dim3(LL / 128, 2, NB), 256>>>(bo, out);
}

// round 12
// speedup vs baseline: 1.0206x; 1.0206x over previous
#include <cuda_runtime.h>
#include <cuda_fp16.h>
#include <math.h>
#include <stdint.h>

#define NB 8
#define CC 256
#define HH 8
#define DD 32
#define LL 2048
#define SCALE 0.0625f            // C^-0.5 = 1/16
#define LOG2E 1.44269504089f

// Scratch (__device__ globals; allocation-free rule)
__device__ uint4 g_q_u[NB * CC * LL / 8];   // half [nh][l][32], SCALE*LOG2E folded
__device__ uint4 g_k_u[NB * CC * LL / 8];   // half [nh][l][32]
__device__ uint4 g_v_u[NB * CC * LL / 8];   // half [nh][32][l]
__device__ uint4 g_xt [NB * CC * LL / 8];   // half [n][l][256]  x transposed
__device__ uint4 g_aoh[NB * CC * LL / 8];   // half [n][l][256]  attn out
__device__ uint4 g_wh [4 * CC * CC / 8];    // half [w][o][c]    weights fp16

__device__ __forceinline__ void mma_f16(float c[4], const uint32_t a[4],
                                        uint32_t b0, uint32_t b1) {
    asm volatile(
        "mma.sync.aligned.m16n8k16.row.col.f32.f16.f16.f32 "
        "{%0,%1,%2,%3}, {%4,%5,%6,%7}, {%8,%9}, {%0,%1,%2,%3};"
        : "+f"(c[0]), "+f"(c[1]), "+f"(c[2]), "+f"(c[3])
        : "r"(a[0]), "r"(a[1]), "r"(a[2]), "r"(a[3]), "r"(b0), "r"(b1));
}

__device__ __forceinline__ uint32_t packh2(float a, float b) {
    __half2 h = __floats2half2_rn(a, b);
    return *(uint32_t*)&h;
}

__device__ __forceinline__ uint32_t h2ex2(uint32_t x) {
    uint32_t y;
    asm("ex2.approx.f16x2 %0, %1;" : "=r"(y) : "r"(x));
    return y;
}

__device__ __forceinline__ float h2sum(uint32_t a, uint32_t b) {
    __half2 s = __hadd2(*(__half2*)&a, *(__half2*)&b);
    float2 f = __half22float2(s);
    return f.x + f.y;
}

__device__ __forceinline__ void ldsm_x4(uint32_t& r0, uint32_t& r1,
                                        uint32_t& r2, uint32_t& r3,
                                        uint32_t saddr) {
    asm volatile(
        "ldmatrix.sync.aligned.m8n8.x4.shared.b16 {%0,%1,%2,%3}, [%4];"
        : "=r"(r0), "=r"(r1), "=r"(r2), "=r"(r3) : "r"(saddr));
}

#define CP_ASYNC16(smem_u32, gptr) \
    asm volatile("cp.async.cg.shared.global [%0], [%1], 16;" \
                 :: "r"(smem_u32), "l"(gptr) : "memory")
#define CP_COMMIT()  asm volatile("cp.async.commit_group;" ::: "memory")
#define CP_WAIT0()   asm volatile("cp.async.wait_group 0;" ::: "memory")

// ---------------------------------------------------------------------------
// K0a: weights f32 -> fp16 [w][o][c].  Wq gets SCALE*LOG2E folded.
// ---------------------------------------------------------------------------
__global__ __launch_bounds__(256) void wconv_kernel(
    const float* __restrict__ Wq, const float* __restrict__ Wk,
    const float* __restrict__ Wv, const float* __restrict__ Wo)
{
    const int w = blockIdx.y;
    const float* W = (w == 0) ? Wq : (w == 1) ? Wk : (w == 2) ? Wv : Wo;
    const float s = (w == 0) ? SCALE * LOG2E : 1.0f;
    const int i = (blockIdx.x * 256 + threadIdx.x) * 4;
    const float4 v = *(const float4*)&W[i];
    uint2 h;
    h.x = packh2(v.x * s, v.y * s);
    h.y = packh2(v.z * s, v.w * s);
    *(uint2*)((__half*)g_wh + (size_t)w * CC * CC + i) = h;
}

// ---------------------------------------------------------------------------
// K0b: transpose x [n][c][l] f32 -> xt [n][l][256] fp16
// ---------------------------------------------------------------------------
__global__ __launch_bounds__(256) void transpose_kernel(
    const float* __restrict__ x)
{
    __shared__ float sm[32][33];
    const int l0 = blockIdx.x * 32;
    const int c0 = blockIdx.y * 32;
    const int n  = blockIdx.z;
    const int t  = threadIdx.x;

    const int li = t & 31, ci = t >> 5;
    #pragma unroll
    for (int k = 0; k < 4; k++)
        sm[ci + k * 8][li] = x[((size_t)n * CC + c0 + ci + k * 8) * LL + l0 + li];
    __syncthreads();

    const int l  = t >> 3;
    const int cg = (t & 7) * 4;
    uint2 hi;
    hi.x = packh2(sm[cg + 0][l], sm[cg + 1][l]);
    hi.y = packh2(sm[cg + 2][l], sm[cg + 3][l]);
    *(uint2*)((__half*)g_xt + ((size_t)n * LL + l0 + l) * CC + c0 + cg) = hi;
}

// ---------------------------------------------------------------------------
// 1-pass fp16 GEMM core.  M=128(l) x N=128(o) x K=256, k-chunk 32.
// 2-stage cp.async pipeline: one __syncthreads per chunk, no RF staging.
// Stage s occupies SM + s*10240 halves (Xh 5120 | Bh 5120).
// ---------------------------------------------------------------------------
struct GemmAcc { float c[16][4]; };

__device__ __forceinline__ void gemm_core1(
    const __half* __restrict__ A, const __half* __restrict__ Bsrc,
    __half* SM, GemmAcc& R)
{
    const int tid  = threadIdx.x;
    const int warp = tid >> 5;
    const int lane = tid & 31;
    const int gid  = lane >> 2;
    const int tg   = lane & 3;
    const int warp_ml = (warp & 3) * 32;
    const int warp_no = (warp >> 2) * 64;

    const uint32_t smb  = (uint32_t)__cvta_generic_to_shared(SM);
    const int lr = tid >> 1, cp = (tid & 1) * 16;
    const uint32_t xdst = smb + (lr * 40 + cp) * 2;
    const uint32_t bdst = xdst + 5120 * 2;

    // stage 0: chunk 0
    CP_ASYNC16(xdst,      A    + (size_t)lr * CC + cp);
    CP_ASYNC16(xdst + 16, A    + (size_t)lr * CC + cp + 8);
    CP_ASYNC16(bdst,      Bsrc + (size_t)lr * CC + cp);
    CP_ASYNC16(bdst + 16, Bsrc + (size_t)lr * CC + cp + 8);
    CP_COMMIT();

    #pragma unroll
    for (int i = 0; i < 16; i++)
        R.c[i][0] = R.c[i][1] = R.c[i][2] = R.c[i][3] = 0.0f;

    CP_WAIT0();
    __syncthreads();

    for (int kk = 0; kk < CC; kk += 32) {
        const int st = (kk >> 5) & 1;
        if (kk + 32 < CC) {
            const uint32_t off = (st ^ 1) * 10240 * 2;
            CP_ASYNC16(xdst + off,      A    + (size_t)lr * CC + kk + 32 + cp);
            CP_ASYNC16(xdst + off + 16, A    + (size_t)lr * CC + kk + 32 + cp + 8);
            CP_ASYNC16(bdst + off,      Bsrc + (size_t)lr * CC + kk + 32 + cp);
            CP_ASYNC16(bdst + off + 16, Bsrc + (size_t)lr * CC + kk + 32 + cp + 8);
            CP_COMMIT();
        }

        const uint32_t* Xh32 = (const uint32_t*)(SM + st * 10240);
        const uint32_t* Bh32 = (const uint32_t*)(SM + st * 10240 + 5120);

        #pragma unroll
        for (int ks = 0; ks < 2; ks++) {
            uint32_t a[2][4];
            #pragma unroll
            for (int mt = 0; mt < 2; mt++) {
                const int r = warp_ml + mt * 16;
                const int b0 = (r + gid) * 20 + ks * 8 + tg;
                const int b8 = (r + gid + 8) * 20 + ks * 8 + tg;
                a[mt][0] = Xh32[b0];     a[mt][1] = Xh32[b8];
                a[mt][2] = Xh32[b0 + 4]; a[mt][3] = Xh32[b8 + 4];
            }
            #pragma unroll
            for (int nt = 0; nt < 8; nt++) {
                const int nb = (warp_no + nt * 8 + gid) * 20 + ks * 8 + tg;
                const uint32_t bb0 = Bh32[nb], bb1 = Bh32[nb + 4];
                #pragma unroll
                for (int mt = 0; mt < 2; mt++)
                    mma_f16(R.c[mt * 8 + nt], a[mt], bb0, bb1);
            }
        }

        if (kk + 32 < CC) {
            CP_WAIT0();
            __syncthreads();
        }
    }
}

// ---------------------------------------------------------------------------
// K1: qkv projection.  grid (16, 2, 24 = n*3+w), 256 thr.
// ---------------------------------------------------------------------------
__global__ __launch_bounds__(256) void gemm_qkv_tc()
{
    __shared__ __align__(16) __half SM[20480];   // 2-stage pipe; reused for V stage

    const int l0 = blockIdx.x * 128;
    const int ot = blockIdx.y;
    const int z  = blockIdx.z;
    const int n  = z / 3, w = z % 3;

    GemmAcc R;
    gemm_core1((const __half*)g_xt + ((size_t)n * LL + l0) * CC,
               (const __half*)g_wh + ((size_t)w * CC + ot * 128) * CC,
               SM, R);

    const int tid  = threadIdx.x;
    const int warp = tid >> 5;
    const int lane = tid & 31;
    const int gid  = lane >> 2;
    const int tg   = lane & 3;
    const int warp_ml = (warp & 3) * 32;
    const int warp_no = (warp >> 2) * 64;

    if (w == 2) {
        __syncthreads();
        #pragma unroll
        for (int mt = 0; mt < 2; mt++)
            #pragma unroll
            for (int nt = 0; nt < 8; nt++) {
                const float* c = R.c[mt * 8 + nt];
                const int ol = warp_no + nt * 8 + 2 * tg;
                const int ll = warp_ml + mt * 16 + gid;
                SM[ol * 136 + ll]           = __float2half_rn(c[0]);
                SM[(ol + 1) * 136 + ll]     = __float2half_rn(c[1]);
                SM[ol * 136 + ll + 8]       = __float2half_rn(c[2]);
                SM[(ol + 1) * 136 + ll + 8] = __float2half_rn(c[3]);
            }
        __syncthreads();
        __half* vd = (__half*)g_v_u + (size_t)n * CC * LL;
        #pragma unroll
        for (int i = 0; i < 8; i++) {
            const int idx = i * 256 + tid;
            const int row = idx >> 4;
            const int col = (idx & 15) * 8;
            uint4 vv = *(uint4*)&SM[row * 136 + col];
            *(uint4*)&vd[(size_t)(ot * 128 + row) * LL + l0 + col] = vv;
        }
    } else {
        __half* qk = (__half*)((w == 0) ? g_q_u : g_k_u);
        #pragma unroll
        for (int mt = 0; mt < 2; mt++)
            #pragma unroll
            for (int nt = 0; nt < 8; nt++) {
                const float* c = R.c[mt * 8 + nt];
                const int o = ot * 128 + warp_no + nt * 8 + 2 * tg;
                const int h = o >> 5, d = o & 31;
                const int l = l0 + warp_ml + mt * 16 + gid;
                const size_t base = (size_t)(n * 8 + h) * LL;
                *(uint32_t*)&qk[(base + l) * 32 + d]     = packh2(c[0], c[1]);
                *(uint32_t*)&qk[(base + l + 8) * 32 + d] = packh2(c[2], c[3]);
            }
    }
}

// ---------------------------------------------------------------------------
// K2: flash attention.  BQ=256 (2 m-tiles/warp), BK=128 per barrier
// (2 x 64 sub-tiles), double-buffered cp.async smem, ldmatrix.x4 frags,
// interleaved ex2/PV.  Row sums on the FMA pipe (HADD2 + f32 accum) —
// no ones-column MMA.  2 CTAs/SM.
// ---------------------------------------------------------------------------
#define KSUB (64 * 72)               // halves per K sub-tile
#define VSUB (32 * 72)               // halves per V sub-tile
#define KSUBB (KSUB * 2)             // bytes
#define VSUBB (VSUB * 2)
#define VBASE (4 * KSUBB)            // V region byte offset
#define ATTN_SMEM_BYTES (4 * KSUBB + 4 * VSUBB)   // 55296 B

__global__ __launch_bounds__(256, 2) void attn_kernel()
{
    extern __shared__ __align__(16) __half sm[];

    const int l0 = blockIdx.x * 256;
    const int nh = blockIdx.y;
    const __half* Qh = (const __half*)g_q_u + (size_t)nh * LL * 32;
    const __half* Kh = (const __half*)g_k_u + (size_t)nh * LL * 32;
    const __half* Vh = (const __half*)g_v_u + (size_t)nh * DD * LL;

    const int tid  = threadIdx.x;
    const int lane = tid & 31;
    const int gid  = lane >> 2;
    const int tg   = lane & 3;
    const int qb   = (tid >> 5) * 32;           // 32 q-rows per warp

    const uint32_t smb   = (uint32_t)__cvta_generic_to_shared(sm);
    const uint32_t ldrow = (lane & 7) * 144 + (lane >> 3) * 16;

    // Staging maps (cp.async, 16B each)
    const int kr   = tid >> 2;            // K row within sub
    const int kc   = tid & 3;             // 16B chunk in row
    const int vd   = tid >> 4;            // V d within 16-row group
    const int vsub = (tid >> 3) & 1;
    const int vci  = tid & 7;
    const uint32_t ksm0 = smb + kr * 144 + kc * 16;
    const uint32_t vsm0 = smb + VBASE + vsub * VSUBB + vd * 144 + vci * 16;

    // Prologue: tile 0 into buffer 0 via cp.async
    #pragma unroll
    for (int i = 0; i < 2; i++) {
        CP_ASYNC16(ksm0 + i * KSUBB, &Kh[(size_t)(i * 64 + kr) * 32 + kc * 8]);
        CP_ASYNC16(vsm0 + i * 16 * 144, &Vh[(size_t)(i * 16 + vd) * LL + (tid & 15) * 8]);
    }
    CP_COMMIT();

    // Q A-frags: 2 m-tiles x 2 k-steps (overlaps with async loads)
    uint32_t aq[2][2][4];
    #pragma unroll
    for (int mt = 0; mt < 2; mt++)
        #pragma unroll
        for (int ks = 0; ks < 2; ks++) {
            const size_t r0 = (size_t)(l0 + qb + mt * 16 + gid) * 32 + ks * 16 + 2 * tg;
            const size_t r8 = r0 + 8 * 32;
            aq[mt][ks][0] = *(const uint32_t*)&Qh[r0];
            aq[mt][ks][1] = *(const uint32_t*)&Qh[r8];
            aq[mt][ks][2] = *(const uint32_t*)&Qh[r0 + 8];
            aq[mt][ks][3] = *(const uint32_t*)&Qh[r8 + 8];
        }

    float o[2][4][4] = {};
    float rs[2][2] = {};                 // per-thread partial row sums

    CP_WAIT0();
    __syncthreads();

    int p = 0;
    for (int kt = 0; kt < LL; kt += 128, p ^= 1) {
        const bool more = (kt + 128 < LL);
        if (more) {
            const uint32_t kb = ksm0 + (p ^ 1) * 2 * KSUBB;
            const uint32_t vb2 = vsm0 + (p ^ 1) * 2 * VSUBB;
            #pragma unroll
            for (int i = 0; i < 2; i++) {
                CP_ASYNC16(kb + i * KSUBB,
                           &Kh[(size_t)(kt + 128 + i * 64 + kr) * 32 + kc * 8]);
                CP_ASYNC16(vb2 + i * 16 * 144,
                           &Vh[(size_t)(i * 16 + vd) * LL + kt + 128 + (tid & 15) * 8]);
            }
            CP_COMMIT();
        }

        #pragma unroll
        for (int sub = 0; sub < 2; sub++) {
            const uint32_t kA = smb + (p * 2 + sub) * KSUBB + ldrow;
            const uint32_t vA = smb + VBASE + (p * 2 + sub) * VSUBB + ldrow;

            #pragma unroll
            for (int half = 0; half < 2; half++) {
                // S' for nt = 4*half .. 4*half+3, both m-tiles
                float c0[4][4], c1[4][4];
                #pragma unroll
                for (int nt4 = 0; nt4 < 4; nt4++) {
                    uint32_t kb0, kb1, kb2, kb3;
                    ldsm_x4(kb0, kb1, kb2, kb3, kA + (half * 4 + nt4) * 1152);
                    c0[nt4][0] = c0[nt4][1] = c0[nt4][2] = c0[nt4][3] = 0.0f;
                    c1[nt4][0] = c1[nt4][1] = c1[nt4][2] = c1[nt4][3] = 0.0f;
                    mma_f16(c0[nt4], aq[0][0], kb0, kb1);
                    mma_f16(c0[nt4], aq[0][1], kb2, kb3);
                    mma_f16(c1[nt4], aq[1][0], kb0, kb1);
                    mma_f16(c1[nt4], aq[1][1], kb2, kb3);
                }

                // V frags for this half, then 2 s-steps
                uint32_t vb[4][4];
                #pragma unroll
                for (int ntv = 0; ntv < 4; ntv++)
                    ldsm_x4(vb[ntv][0], vb[ntv][1], vb[ntv][2], vb[ntv][3],
                            vA + ntv * 1152 + half * 64);

                #pragma unroll
                for (int sh = 0; sh < 2; sh++) {
                    uint32_t pa[4];
                    // m-tile 0
                    pa[0] = h2ex2(packh2(c0[2 * sh][0],     c0[2 * sh][1]));
                    pa[1] = h2ex2(packh2(c0[2 * sh][2],     c0[2 * sh][3]));
                    pa[2] = h2ex2(packh2(c0[2 * sh + 1][0], c0[2 * sh + 1][1]));
                    pa[3] = h2ex2(packh2(c0[2 * sh + 1][2], c0[2 * sh + 1][3]));
                    #pragma unroll
                    for (int ntv = 0; ntv < 4; ntv++)
                        mma_f16(o[0][ntv], pa, vb[ntv][2 * sh], vb[ntv][2 * sh + 1]);
                    rs[0][0] += h2sum(pa[0], pa[2]);   // row gid
                    rs[0][1] += h2sum(pa[1], pa[3]);   // row gid+8
                    // m-tile 1
                    pa[0] = h2ex2(packh2(c1[2 * sh][0],     c1[2 * sh][1]));
                    pa[1] = h2ex2(packh2(c1[2 * sh][2],     c1[2 * sh][3]));
                    pa[2] = h2ex2(packh2(c1[2 * sh + 1][0], c1[2 * sh + 1][1]));
                    pa[3] = h2ex2(packh2(c1[2 * sh + 1][2], c1[2 * sh + 1][3]));
                    #pragma unroll
                    for (int ntv = 0; ntv < 4; ntv++)
                        mma_f16(o[1][ntv], pa, vb[ntv][2 * sh], vb[ntv][2 * sh + 1]);
                    rs[1][0] += h2sum(pa[0], pa[2]);
                    rs[1][1] += h2sum(pa[1], pa[3]);
                }
            }
        }

        if (more) {
            CP_WAIT0();
            __syncthreads();
        }
    }

    // Epilogue: reduce row sums across the tg quad, normalize, write fp16
    const int n = nh >> 3, h = nh & 7;
    __half* aoh = (__half*)g_aoh;
    #pragma unroll
    for (int mt = 0; mt < 2; mt++) {
        float r0 = rs[mt][0], r1 = rs[mt][1];
        r0 += __shfl_xor_sync(0xffffffffu, r0, 1);
        r0 += __shfl_xor_sync(0xffffffffu, r0, 2);
        r1 += __shfl_xor_sync(0xffffffffu, r1, 1);
        r1 += __shfl_xor_sync(0xffffffffu, r1, 2);
        const float inv0 = 1.0f / r0;
        const float inv1 = 1.0f / r1;
        #pragma unroll
        for (int ntv = 0; ntv < 4; ntv++) {
            const int d = h * 32 + ntv * 8 + 2 * tg;
            const int lr = l0 + qb + mt * 16 + gid;
            const size_t a0 = ((size_t)n * LL + lr) * CC + d;
            const size_t a1 = ((size_t)n * LL + lr + 8) * CC + d;
            *(uint32_t*)&aoh[a0] = packh2(o[mt][ntv][0] * inv0, o[mt][ntv][1] * inv0);
            *(uint32_t*)&aoh[a1] = packh2(o[mt][ntv][2] * inv1, o[mt][ntv][3] * inv1);
        }
    }
}

// ---------------------------------------------------------------------------
// K3: output projection: out = Wo @ ao + bo (f32 out).  grid (16, 2, 8).
// ---------------------------------------------------------------------------
__global__ __launch_bounds__(256) void gemm_proj_tc(
    const float* __restrict__ bo,
    float* __restrict__ out)
{
    __shared__ __align__(16) __half SM[20480];

    const int l0 = blockIdx.x * 128;
    const int ot = blockIdx.y;
    const int n  = blockIdx.z;

    GemmAcc R;
    gemm_core1((const __half*)g_aoh + ((size_t)n * LL + l0) * CC,
               (const __half*)g_wh + ((size_t)3 * CC + ot * 128) * CC,
               SM, R);

    const int tid  = threadIdx.x;
    const int warp = tid >> 5;
    const int lane = tid & 31;
    const int gid  = lane >> 2;
    const int tg   = lane & 3;
    const int warp_ml = (warp & 3) * 32;
    const int warp_no = (warp >> 2) * 64;

    float* base = out + (size_t)n * CC * LL;
    #pragma unroll
    for (int mt = 0; mt < 2; mt++)
        #pragma unroll
        for (int nt = 0; nt < 8; nt++) {
            const float* c = R.c[mt * 8 + nt];
            const int o = ot * 128 + warp_no + nt * 8 + 2 * tg;
            const int l = l0 + warp_ml + mt * 16 + gid;
            const float b0v = bo[o], b1v = bo[o + 1];
            base[(size_t)o * LL + l]           = c[0] + b0v;
            base[(size_t)(o + 1) * LL + l]     = c[1] + b1v;
            base[(size_t)o * LL + l + 8]       = c[2] + b0v;
            base[(size_t)(o + 1) * LL + l + 8] = c[3] + b1v;
        }
}

// ---------------------------------------------------------------------------
extern "C" void kernel_launch(void* const* d_in, const int* in_sizes, int n_in,
                              void* d_out, int out_size)
{
    const float* x  = (const float*)d_in[0];
    const float* Wq = (const float*)d_in[1];
    const float* Wk = (const float*)d_in[2];
    const float* Wv = (const float*)d_in[3];
    const float* Wo = (const float*)d_in[4];
    const float* bo = (const float*)d_in[5];
    float* out = (float*)d_out;

    cudaFuncSetAttribute(attn_kernel,
                         cudaFuncAttributeMaxDynamicSharedMemorySize,
                         ATTN_SMEM_BYTES);

    wconv_kernel<<<dim3(CC * CC / 1024, 4), 256>>>(Wq, Wk, Wv, Wo);
    transpose_kernel<<<dim3(LL / 32, CC / 32, NB), 256>>>(x);
    gemm_qkv_tc<<<dim3(LL / 128, 2, NB * 3), 256>>>();
    attn_kernel<<<dim3(LL / 256, NB * HH), 256, ATTN_SMEM_BYTES>>>();
    gemm_proj_tc<<<dim3(LL / 128, 2, NB), 256>>>(bo, out);
}

// round 13
// speedup vs baseline: 1.0903x; 1.0683x over previous
#include <cuda_runtime.h>
#include <cuda_fp16.h>
#include <math.h>
#include <stdint.h>

#define NB 8
#define CC 256
#define HH 8
#define DD 32
#define LL 2048
#define SCALE 0.0625f            // C^-0.5 = 1/16
#define LOG2E 1.44269504089f

// Scratch (__device__ globals; allocation-free rule)
__device__ uint4 g_q_u[NB * CC * LL / 8];   // half [nh][l][32], SCALE*LOG2E folded
__device__ uint4 g_k_u[NB * CC * LL / 8];   // half [nh][l][32]
__device__ uint4 g_v_u[NB * CC * LL / 8];   // half [nh][32][l]
__device__ uint4 g_xt [NB * CC * LL / 8];   // half [n][l][256]  x transposed
__device__ uint4 g_aoh[NB * CC * LL / 8];   // half [n][l][256]  attn out
__device__ uint4 g_wh [4 * CC * CC / 8];    // half [w][o][c]    weights fp16

__device__ __forceinline__ void mma_f16(float c[4], const uint32_t a[4],
                                        uint32_t b0, uint32_t b1) {
    asm volatile(
        "mma.sync.aligned.m16n8k16.row.col.f32.f16.f16.f32 "
        "{%0,%1,%2,%3}, {%4,%5,%6,%7}, {%8,%9}, {%0,%1,%2,%3};"
        : "+f"(c[0]), "+f"(c[1]), "+f"(c[2]), "+f"(c[3])
        : "r"(a[0]), "r"(a[1]), "r"(a[2]), "r"(a[3]), "r"(b0), "r"(b1));
}

__device__ __forceinline__ uint32_t packh2(float a, float b) {
    __half2 h = __floats2half2_rn(a, b);
    return *(uint32_t*)&h;
}

__device__ __forceinline__ uint32_t h2ex2(uint32_t x) {
    uint32_t y;
    asm("ex2.approx.f16x2 %0, %1;" : "=r"(y) : "r"(x));
    return y;
}

__device__ __forceinline__ void ldsm_x4(uint32_t& r0, uint32_t& r1,
                                        uint32_t& r2, uint32_t& r3,
                                        uint32_t saddr) {
    asm volatile(
        "ldmatrix.sync.aligned.m8n8.x4.shared.b16 {%0,%1,%2,%3}, [%4];"
        : "=r"(r0), "=r"(r1), "=r"(r2), "=r"(r3) : "r"(saddr));
}

#define CP_ASYNC16(smem_u32, gptr) \
    asm volatile("cp.async.cg.shared.global [%0], [%1], 16;" \
                 :: "r"(smem_u32), "l"(gptr) : "memory")
#define CP_COMMIT()  asm volatile("cp.async.commit_group;" ::: "memory")
#define CP_WAIT0()   asm volatile("cp.async.wait_group 0;" ::: "memory")

// ---------------------------------------------------------------------------
// K0a: weights f32 -> fp16 [w][o][c].  Wq gets SCALE*LOG2E folded.
// ---------------------------------------------------------------------------
__global__ __launch_bounds__(256) void wconv_kernel(
    const float* __restrict__ Wq, const float* __restrict__ Wk,
    const float* __restrict__ Wv, const float* __restrict__ Wo)
{
    const int w = blockIdx.y;
    const float* W = (w == 0) ? Wq : (w == 1) ? Wk : (w == 2) ? Wv : Wo;
    const float s = (w == 0) ? SCALE * LOG2E : 1.0f;
    const int i = (blockIdx.x * 256 + threadIdx.x) * 4;
    const float4 v = *(const float4*)&W[i];
    uint2 h;
    h.x = packh2(v.x * s, v.y * s);
    h.y = packh2(v.z * s, v.w * s);
    *(uint2*)((__half*)g_wh + (size_t)w * CC * CC + i) = h;
}

// ---------------------------------------------------------------------------
// K0b: transpose x [n][c][l] f32 -> xt [n][l][256] fp16
// ---------------------------------------------------------------------------
__global__ __launch_bounds__(256) void transpose_kernel(
    const float* __restrict__ x)
{
    __shared__ float sm[32][33];
    const int l0 = blockIdx.x * 32;
    const int c0 = blockIdx.y * 32;
    const int n  = blockIdx.z;
    const int t  = threadIdx.x;

    const int li = t & 31, ci = t >> 5;
    #pragma unroll
    for (int k = 0; k < 4; k++)
        sm[ci + k * 8][li] = x[((size_t)n * CC + c0 + ci + k * 8) * LL + l0 + li];
    __syncthreads();

    const int l  = t >> 3;
    const int cg = (t & 7) * 4;
    uint2 hi;
    hi.x = packh2(sm[cg + 0][l], sm[cg + 1][l]);
    hi.y = packh2(sm[cg + 2][l], sm[cg + 3][l]);
    *(uint2*)((__half*)g_xt + ((size_t)n * LL + l0 + l) * CC + c0 + cg) = hi;
}

// ---------------------------------------------------------------------------
// 1-pass fp16 GEMM core.  M=128(l) x N=128(o) x K=256, k-chunk 32.
// 2-stage cp.async pipeline: one __syncthreads per chunk, no RF staging.
// Stage s occupies SM + s*10240 halves (Xh 5120 | Bh 5120).
// ---------------------------------------------------------------------------
struct GemmAcc { float c[16][4]; };

__device__ __forceinline__ void gemm_core1(
    const __half* __restrict__ A, const __half* __restrict__ Bsrc,
    __half* SM, GemmAcc& R)
{
    const int tid  = threadIdx.x;
    const int warp = tid >> 5;
    const int lane = tid & 31;
    const int gid  = lane >> 2;
    const int tg   = lane & 3;
    const int warp_ml = (warp & 3) * 32;
    const int warp_no = (warp >> 2) * 64;

    const uint32_t smb  = (uint32_t)__cvta_generic_to_shared(SM);
    const int lr = tid >> 1, cp = (tid & 1) * 16;
    const uint32_t xdst = smb + (lr * 40 + cp) * 2;
    const uint32_t bdst = xdst + 5120 * 2;

    // stage 0: chunk 0
    CP_ASYNC16(xdst,      A    + (size_t)lr * CC + cp);
    CP_ASYNC16(xdst + 16, A    + (size_t)lr * CC + cp + 8);
    CP_ASYNC16(bdst,      Bsrc + (size_t)lr * CC + cp);
    CP_ASYNC16(bdst + 16, Bsrc + (size_t)lr * CC + cp + 8);
    CP_COMMIT();

    #pragma unroll
    for (int i = 0; i < 16; i++)
        R.c[i][0] = R.c[i][1] = R.c[i][2] = R.c[i][3] = 0.0f;

    CP_WAIT0();
    __syncthreads();

    for (int kk = 0; kk < CC; kk += 32) {
        const int st = (kk >> 5) & 1;
        if (kk + 32 < CC) {
            const uint32_t off = (st ^ 1) * 10240 * 2;
            CP_ASYNC16(xdst + off,      A    + (size_t)lr * CC + kk + 32 + cp);
            CP_ASYNC16(xdst + off + 16, A    + (size_t)lr * CC + kk + 32 + cp + 8);
            CP_ASYNC16(bdst + off,      Bsrc + (size_t)lr * CC + kk + 32 + cp);
            CP_ASYNC16(bdst + off + 16, Bsrc + (size_t)lr * CC + kk + 32 + cp + 8);
            CP_COMMIT();
        }

        const uint32_t* Xh32 = (const uint32_t*)(SM + st * 10240);
        const uint32_t* Bh32 = (const uint32_t*)(SM + st * 10240 + 5120);

        #pragma unroll
        for (int ks = 0; ks < 2; ks++) {
            uint32_t a[2][4];
            #pragma unroll
            for (int mt = 0; mt < 2; mt++) {
                const int r = warp_ml + mt * 16;
                const int b0 = (r + gid) * 20 + ks * 8 + tg;
                const int b8 = (r + gid + 8) * 20 + ks * 8 + tg;
                a[mt][0] = Xh32[b0];     a[mt][1] = Xh32[b8];
                a[mt][2] = Xh32[b0 + 4]; a[mt][3] = Xh32[b8 + 4];
            }
            #pragma unroll
            for (int nt = 0; nt < 8; nt++) {
                const int nb = (warp_no + nt * 8 + gid) * 20 + ks * 8 + tg;
                const uint32_t bb0 = Bh32[nb], bb1 = Bh32[nb + 4];
                #pragma unroll
                for (int mt = 0; mt < 2; mt++)
                    mma_f16(R.c[mt * 8 + nt], a[mt], bb0, bb1);
            }
        }

        if (kk + 32 < CC) {
            CP_WAIT0();
            __syncthreads();
        }
    }
}

// ---------------------------------------------------------------------------
// K1: qkv projection.  grid (16, 2, 24 = n*3+w), 256 thr.
// ---------------------------------------------------------------------------
__global__ __launch_bounds__(256) void gemm_qkv_tc()
{
    __shared__ __align__(16) __half SM[20480];   // 2-stage pipe; reused for V stage

    const int l0 = blockIdx.x * 128;
    const int ot = blockIdx.y;
    const int z  = blockIdx.z;
    const int n  = z / 3, w = z % 3;

    GemmAcc R;
    gemm_core1((const __half*)g_xt + ((size_t)n * LL + l0) * CC,
               (const __half*)g_wh + ((size_t)w * CC + ot * 128) * CC,
               SM, R);

    const int tid  = threadIdx.x;
    const int warp = tid >> 5;
    const int lane = tid & 31;
    const int gid  = lane >> 2;
    const int tg   = lane & 3;
    const int warp_ml = (warp & 3) * 32;
    const int warp_no = (warp >> 2) * 64;

    if (w == 2) {
        __syncthreads();
        #pragma unroll
        for (int mt = 0; mt < 2; mt++)
            #pragma unroll
            for (int nt = 0; nt < 8; nt++) {
                const float* c = R.c[mt * 8 + nt];
                const int ol = warp_no + nt * 8 + 2 * tg;
                const int ll = warp_ml + mt * 16 + gid;
                SM[ol * 136 + ll]           = __float2half_rn(c[0]);
                SM[(ol + 1) * 136 + ll]     = __float2half_rn(c[1]);
                SM[ol * 136 + ll + 8]       = __float2half_rn(c[2]);
                SM[(ol + 1) * 136 + ll + 8] = __float2half_rn(c[3]);
            }
        __syncthreads();
        __half* vd = (__half*)g_v_u + (size_t)n * CC * LL;
        #pragma unroll
        for (int i = 0; i < 8; i++) {
            const int idx = i * 256 + tid;
            const int row = idx >> 4;
            const int col = (idx & 15) * 8;
            uint4 vv = *(uint4*)&SM[row * 136 + col];
            *(uint4*)&vd[(size_t)(ot * 128 + row) * LL + l0 + col] = vv;
        }
    } else {
        __half* qk = (__half*)((w == 0) ? g_q_u : g_k_u);
        #pragma unroll
        for (int mt = 0; mt < 2; mt++)
            #pragma unroll
            for (int nt = 0; nt < 8; nt++) {
                const float* c = R.c[mt * 8 + nt];
                const int o = ot * 128 + warp_no + nt * 8 + 2 * tg;
                const int h = o >> 5, d = o & 31;
                const int l = l0 + warp_ml + mt * 16 + gid;
                const size_t base = (size_t)(n * 8 + h) * LL;
                *(uint32_t*)&qk[(base + l) * 32 + d]     = packh2(c[0], c[1]);
                *(uint32_t*)&qk[(base + l + 8) * 32 + d] = packh2(c[2], c[3]);
            }
    }
}

// ---------------------------------------------------------------------------
// K2: flash attention (Round-10 configuration — measured best at 98.4us).
// BQ=128, BK=128 per barrier (2 x 64 sub-tiles), double-buffered dynamic
// smem with register prefetch, ldmatrix.x4 fragment loads, interleaved
// ex2/PV, ones-column row-sum MMA.  3 CTAs/SM.
// ---------------------------------------------------------------------------
#define KSUB (64 * 72)               // halves per K sub-tile
#define VSUB (32 * 72)               // halves per V sub-tile
#define ATTN_SMEM_BYTES ((4 * KSUB + 4 * VSUB) * 2)   // 55296 B

__global__ __launch_bounds__(256, 3) void attn_kernel()
{
    extern __shared__ __align__(16) __half sm[];

    const int l0 = blockIdx.x * 128;
    const int nh = blockIdx.y;
    const __half* Qh = (const __half*)g_q_u + (size_t)nh * LL * 32;
    const __half* Kh = (const __half*)g_k_u + (size_t)nh * LL * 32;
    const __half* Vh = (const __half*)g_v_u + (size_t)nh * DD * LL;

    const int tid  = threadIdx.x;
    const int lane = tid & 31;
    const int gid  = lane >> 2;
    const int tg   = lane & 3;
    const int qb   = (tid >> 5) * 16;

    uint32_t aq[2][4];
    #pragma unroll
    for (int ks = 0; ks < 2; ks++) {
        aq[ks][0] = *(const uint32_t*)&Qh[(size_t)(l0 + qb + gid    ) * 32 + ks * 16 + 2 * tg    ];
        aq[ks][1] = *(const uint32_t*)&Qh[(size_t)(l0 + qb + gid + 8) * 32 + ks * 16 + 2 * tg    ];
        aq[ks][2] = *(const uint32_t*)&Qh[(size_t)(l0 + qb + gid    ) * 32 + ks * 16 + 2 * tg + 8];
        aq[ks][3] = *(const uint32_t*)&Qh[(size_t)(l0 + qb + gid + 8) * 32 + ks * 16 + 2 * tg + 8];
    }

    // Staging maps
    const int kr   = tid >> 2;            // K row within sub
    const int kc   = tid & 3;             // 16B chunk in row
    const int vd   = tid >> 4;            // V d within 16-row group
    const int vsub = (tid >> 3) & 1;
    const int vci  = tid & 7;

    // ldmatrix per-lane row address offset (byte units): row stride 144B
    const uint32_t smb   = (uint32_t)__cvta_generic_to_shared(sm);
    const uint32_t ldrow = (lane & 7) * 144 + (lane >> 3) * 16;

    float o[4][4] = {};
    float oS[4] = {};
    const uint32_t bones = (gid == 0) ? 0x3C003C00u : 0u;

    // Prologue: tile 0 (128 wide) into buffer 0
    #pragma unroll
    for (int i = 0; i < 2; i++) {
        uint4 kv = *(const uint4*)&Kh[(size_t)(i * 64 + kr) * 32 + kc * 8];
        *(uint4*)&sm[i * KSUB + kr * 72 + kc * 8] = kv;
        uint4 vv = *(const uint4*)&Vh[(size_t)(i * 16 + vd) * LL + (tid & 15) * 8];
        *(uint4*)&sm[4 * KSUB + vsub * VSUB + (i * 16 + vd) * 72 + vci * 8] = vv;
    }
    __syncthreads();

    int p = 0;
    for (int kt = 0; kt < LL; kt += 128, p ^= 1) {
        const bool more = (kt + 128 < LL);
        uint4 kn[2], vn[2];
        if (more) {
            #pragma unroll
            for (int i = 0; i < 2; i++) {
                kn[i] = *(const uint4*)&Kh[(size_t)(kt + 128 + i * 64 + kr) * 32 + kc * 8];
                vn[i] = *(const uint4*)&Vh[(size_t)(i * 16 + vd) * LL + kt + 128 + (tid & 15) * 8];
            }
        }

        #pragma unroll
        for (int sub = 0; sub < 2; sub++) {
            const uint32_t kA = smb + (p * 2 + sub) * (KSUB * 2) + ldrow;
            const uint32_t vA = smb + 4 * (KSUB * 2) + (p * 2 + sub) * (VSUB * 2) + ldrow;

            // S' = (Q*scale*log2e) K^T  — one LDSM.x4 per n-tile
            float c[8][4];
            #pragma unroll
            for (int nt = 0; nt < 8; nt++) {
                uint32_t kb0, kb1, kb2, kb3;
                ldsm_x4(kb0, kb1, kb2, kb3, kA + nt * 1152);
                c[nt][0] = c[nt][1] = c[nt][2] = c[nt][3] = 0.0f;
                mma_f16(c[nt], aq[0], kb0, kb1);
                mma_f16(c[nt], aq[1], kb2, kb3);
            }

            // PV interleaved with ex2, two s-steps per V LDSM pass
            #pragma unroll
            for (int sp = 0; sp < 2; sp++) {
                uint32_t vb[4][4];
                #pragma unroll
                for (int ntv = 0; ntv < 4; ntv++)
                    ldsm_x4(vb[ntv][0], vb[ntv][1], vb[ntv][2], vb[ntv][3],
                            vA + ntv * 1152 + sp * 64);
                #pragma unroll
                for (int sh = 0; sh < 2; sh++) {
                    const int s = sp * 2 + sh;
                    uint32_t pa[4];
                    pa[0] = h2ex2(packh2(c[2 * s][0],     c[2 * s][1]));
                    pa[1] = h2ex2(packh2(c[2 * s][2],     c[2 * s][3]));
                    pa[2] = h2ex2(packh2(c[2 * s + 1][0], c[2 * s + 1][1]));
                    pa[3] = h2ex2(packh2(c[2 * s + 1][2], c[2 * s + 1][3]));
                    #pragma unroll
                    for (int ntv = 0; ntv < 4; ntv++)
                        mma_f16(o[ntv], pa, vb[ntv][2 * sh], vb[ntv][2 * sh + 1]);
                    mma_f16(oS, pa, bones, bones);
                }
            }
        }

        if (more) {
            #pragma unroll
            for (int i = 0; i < 2; i++) {
                *(uint4*)&sm[(p ^ 1) * 2 * KSUB + i * KSUB + kr * 72 + kc * 8] = kn[i];
                *(uint4*)&sm[4 * KSUB + ((p ^ 1) * 2 + vsub) * VSUB + (i * 16 + vd) * 72 + vci * 8] = vn[i];
            }
            __syncthreads();
        }
    }

    // Epilogue: broadcast row sums from tg==0 lanes, normalize, write fp16
    const float l0v = __shfl_sync(0xffffffffu, oS[0], lane & 28);
    const float l1v = __shfl_sync(0xffffffffu, oS[2], lane & 28);
    const float inv0 = 1.0f / l0v;
    const float inv1 = 1.0f / l1v;

    const int n = nh >> 3, h = nh & 7;
    __half* aoh = (__half*)g_aoh;
    #pragma unroll
    for (int ntv = 0; ntv < 4; ntv++) {
        const int d = h * 32 + ntv * 8 + 2 * tg;
        const size_t a0 = ((size_t)n * LL + l0 + qb + gid) * CC + d;
        const size_t a1 = ((size_t)n * LL + l0 + qb + gid + 8) * CC + d;
        *(uint32_t*)&aoh[a0] = packh2(o[ntv][0] * inv0, o[ntv][1] * inv0);
        *(uint32_t*)&aoh[a1] = packh2(o[ntv][2] * inv1, o[ntv][3] * inv1);
    }
}

// ---------------------------------------------------------------------------
// K3: output projection: out = Wo @ ao + bo (f32 out).  grid (16, 2, 8).
// ---------------------------------------------------------------------------
__global__ __launch_bounds__(256) void gemm_proj_tc(
    const float* __restrict__ bo,
    float* __restrict__ out)
{
    __shared__ __align__(16) __half SM[20480];

    const int l0 = blockIdx.x * 128;
    const int ot = blockIdx.y;
    const int n  = blockIdx.z;

    GemmAcc R;
    gemm_core1((const __half*)g_aoh + ((size_t)n * LL + l0) * CC,
               (const __half*)g_wh + ((size_t)3 * CC + ot * 128) * CC,
               SM, R);

    const int tid  = threadIdx.x;
    const int warp = tid >> 5;
    const int lane = tid & 31;
    const int gid  = lane >> 2;
    const int tg   = lane & 3;
    const int warp_ml = (warp & 3) * 32;
    const int warp_no = (warp >> 2) * 64;

    float* base = out + (size_t)n * CC * LL;
    #pragma unroll
    for (int mt = 0; mt < 2; mt++)
        #pragma unroll
        for (int nt = 0; nt < 8; nt++) {
            const float* c = R.c[mt * 8 + nt];
            const int o = ot * 128 + warp_no + nt * 8 + 2 * tg;
            const int l = l0 + warp_ml + mt * 16 + gid;
            const float b0v = bo[o], b1v = bo[o + 1];
            base[(size_t)o * LL + l]           = c[0] + b0v;
            base[(size_t)(o + 1) * LL + l]     = c[1] + b1v;
            base[(size_t)o * LL + l + 8]       = c[2] + b0v;
            base[(size_t)(o + 1) * LL + l + 8] = c[3] + b1v;
        }
}

// ---------------------------------------------------------------------------
extern "C" void kernel_launch(void* const* d_in, const int* in_sizes, int n_in,
                              void* d_out, int out_size)
{
    const float* x  = (const float*)d_in[0];
    const float* Wq = (const float*)d_in[1];
    const float* Wk = (const float*)d_in[2];
    const float* Wv = (const float*)d_in[3];
    const float* Wo = (const float*)d_in[4];
    const float* bo = (const float*)d_in[5];
    float* out = (float*)d_out;

    cudaFuncSetAttribute(attn_kernel,
                         cudaFuncAttributeMaxDynamicSharedMemorySize,
                         ATTN_SMEM_BYTES);

    wconv_kernel<<<dim3(CC * CC / 1024, 4), 256>>>(Wq, Wk, Wv, Wo);
    transpose_kernel<<<dim3(LL / 32, CC / 32, NB), 256>>>(x);
    gemm_qkv_tc<<<dim3(LL / 128, 2, NB * 3), 256>>>();
    attn_kernel<<<dim3(LL / 128, NB * HH), 256, ATTN_SMEM_BYTES>>>();
    gemm_proj_tc<<<dim3(LL / 128, 2, NB), 256>>>(bo, out);
}